// round 1
// baseline (speedup 1.0000x reference)
#include <cuda_runtime.h>
#include <cstdint>

#define T_STEPS 512
#define BATCH   32
#define HID     512
#define G3      1536
#define LN_EPS  1e-5f
#define NBLK    128          // recurrent grid (64 CTAs per direction)

// ---------------- scratch (static device globals; no allocation) ----------------
__device__ float    g_ax[(size_t)2 * 512 * 32 * 1536];   // LN(x@Wx+bx) per dir  (201 MB)
__device__ float    g_seq[(size_t)2 * 512 * 32 * 512];   // layer-0 outputs (fwd, bwd)
__device__ float    g_h[2 * 32 * 512];                   // current hidden state per dir
__device__ float    g_stats[2 * 2 * 32 * 3 * 2];         // [parity][dir][b][gate][sum,sumsq]
__device__ unsigned g_bar;                               // grid barrier counter

// ============================================================================
// Input GEMM: raw_ax[dir][m][col] = in[m][:] @ Wx[dir][:,col] + bx[dir][col]
// m = t*B + b (rows contiguous with lda=512). 64x64x16 fp32 tile, 256 threads.
// ============================================================================
#define BM 64
#define BN 64
#define BK 16

__global__ void gemm_ax_kernel(const float* __restrict__ x,
                               const float* __restrict__ Wx,
                               const float* __restrict__ bx,
                               int layer)
{
    const int dir = blockIdx.z;
    const float* A = (layer == 0) ? x
                                  : (g_seq + (size_t)dir * T_STEPS * BATCH * HID);
    const int wsel = 2 * layer + dir;
    const float* Bw   = Wx + (size_t)wsel * 512 * 1536;
    const float* bias = bx + (size_t)wsel * 1536;
    float* C = g_ax + (size_t)dir * 16384 * 1536;

    const int m0 = blockIdx.y * BM;
    const int n0 = blockIdx.x * BN;

    __shared__ float As[BK][BM + 4];   // pitch 68 floats: keeps float4 alignment
    __shared__ float Bs[BK][BN];

    const int tid = threadIdx.x;
    const int tx = tid & 15;           // 0..15 -> 4 output cols
    const int ty = tid >> 4;           // 0..15 -> 4 output rows

    float acc[4][4];
#pragma unroll
    for (int i = 0; i < 4; ++i)
#pragma unroll
        for (int j = 0; j < 4; ++j) acc[i][j] = 0.f;

    const int arow = tid >> 2, akq = tid & 3;         // A-tile loader map
    const int bkk  = tid >> 4, bjq = tid & 15;        // B-tile loader map

    for (int k0 = 0; k0 < 512; k0 += BK) {
        float4 av = *(const float4*)(A + (size_t)(m0 + arow) * 512 + k0 + akq * 4);
        As[akq * 4 + 0][arow] = av.x;
        As[akq * 4 + 1][arow] = av.y;
        As[akq * 4 + 2][arow] = av.z;
        As[akq * 4 + 3][arow] = av.w;
        *(float4*)&Bs[bkk][bjq * 4] =
            *(const float4*)(Bw + (size_t)(k0 + bkk) * 1536 + n0 + bjq * 4);
        __syncthreads();
#pragma unroll
        for (int kk = 0; kk < BK; ++kk) {
            float4 a = *(const float4*)&As[kk][ty * 4];
            float4 b = *(const float4*)&Bs[kk][tx * 4];
            acc[0][0] = fmaf(a.x, b.x, acc[0][0]); acc[0][1] = fmaf(a.x, b.y, acc[0][1]);
            acc[0][2] = fmaf(a.x, b.z, acc[0][2]); acc[0][3] = fmaf(a.x, b.w, acc[0][3]);
            acc[1][0] = fmaf(a.y, b.x, acc[1][0]); acc[1][1] = fmaf(a.y, b.y, acc[1][1]);
            acc[1][2] = fmaf(a.y, b.z, acc[1][2]); acc[1][3] = fmaf(a.y, b.w, acc[1][3]);
            acc[2][0] = fmaf(a.z, b.x, acc[2][0]); acc[2][1] = fmaf(a.z, b.y, acc[2][1]);
            acc[2][2] = fmaf(a.z, b.z, acc[2][2]); acc[2][3] = fmaf(a.z, b.w, acc[2][3]);
            acc[3][0] = fmaf(a.w, b.x, acc[3][0]); acc[3][1] = fmaf(a.w, b.y, acc[3][1]);
            acc[3][2] = fmaf(a.w, b.z, acc[3][2]); acc[3][3] = fmaf(a.w, b.w, acc[3][3]);
        }
        __syncthreads();
    }

    const float4 bv = *(const float4*)(bias + n0 + tx * 4);
#pragma unroll
    for (int i = 0; i < 4; ++i) {
        float4 o;
        o.x = acc[i][0] + bv.x; o.y = acc[i][1] + bv.y;
        o.z = acc[i][2] + bv.z; o.w = acc[i][3] + bv.w;
        *(float4*)(C + (size_t)(m0 + ty * 4 + i) * 1536 + n0 + tx * 4) = o;
    }
}

// ============================================================================
// LayerNorm over each 512-wide gate chunk of g_ax (in place), then *gx + bex.
// One block (128 threads) per (dir, row, gate).
// ============================================================================
__global__ void ln_ax_kernel(const float* __restrict__ gx,
                             const float* __restrict__ bex,
                             int layer)
{
    const int id   = blockIdx.x;               // 2*16384*3 blocks
    const int gate = id % 3;
    const int row  = (id / 3) & 16383;
    const int dir  = id / (3 * 16384);
    const int wsel = 2 * layer + dir;

    float* p = g_ax + (size_t)dir * 16384 * 1536 + (size_t)row * 1536 + gate * 512;
    const float* gp = gx  + (size_t)wsel * 1536 + gate * 512;
    const float* bp = bex + (size_t)wsel * 1536 + gate * 512;

    const int tid = threadIdx.x;               // 128 threads * 4 elems
    float4 v = *(const float4*)(p + tid * 4);
    float s  = v.x + v.y + v.z + v.w;
    float ss = v.x * v.x + v.y * v.y + v.z * v.z + v.w * v.w;
#pragma unroll
    for (int o = 16; o; o >>= 1) {
        s  += __shfl_xor_sync(0xffffffffu, s,  o);
        ss += __shfl_xor_sync(0xffffffffu, ss, o);
    }
    __shared__ float red[8];
    if ((tid & 31) == 0) { red[tid >> 5] = s; red[4 + (tid >> 5)] = ss; }
    __syncthreads();
    const float ts  = red[0] + red[1] + red[2] + red[3];
    const float tss = red[4] + red[5] + red[6] + red[7];
    const float mu   = ts * (1.f / 512.f);
    const float var  = tss * (1.f / 512.f) - mu * mu;
    const float rstd = rsqrtf(var + LN_EPS);

    const float4 g4 = *(const float4*)(gp + tid * 4);
    const float4 b4 = *(const float4*)(bp + tid * 4);
    float4 o;
    o.x = (v.x - mu) * rstd * g4.x + b4.x;
    o.y = (v.y - mu) * rstd * g4.y + b4.y;
    o.z = (v.z - mu) * rstd * g4.z + b4.z;
    o.w = (v.w - mu) * rstd * g4.w + b4.w;
    *(float4*)(p + tid * 4) = o;
}

// ============================================================================
// Scratch reset (barrier counter + stats) before each recurrent launch.
// ============================================================================
__global__ void init_scratch_kernel()
{
    const int i = threadIdx.x;
    if (i == 0) g_bar = 0u;
    for (int k = i; k < 2 * 2 * 32 * 3 * 2; k += blockDim.x) g_stats[k] = 0.f;
}

// ============================================================================
// Persistent recurrent kernel: both directions of one layer, 512 steps.
// 128 CTAs x 256 thr. CTA (dir, c) owns hidden cols j0..j0+7 across all gates.
// Wh slice (512x24) stays in SMEM for the whole kernel.
// ============================================================================
__device__ __forceinline__ void grid_bar(unsigned& epoch)
{
    __threadfence();
    __syncthreads();
    if (threadIdx.x == 0) {
        atomicAdd(&g_bar, 1u);
        const unsigned target = (++epoch) * (unsigned)NBLK;
        while (*(volatile unsigned*)&g_bar < target) { }
        __threadfence();
    }
    __syncthreads();
}

__global__ void recurrent_kernel(const float* __restrict__ Wh,
                                 const float* __restrict__ bh,
                                 const float* __restrict__ gh,
                                 const float* __restrict__ beh,
                                 const float* __restrict__ h0,
                                 float* __restrict__ out,
                                 int layer, int write_hid)
{
    extern __shared__ float sm[];
    float* Wsh   = sm;                         // [512][24]  12288 f
    float* hsh   = Wsh + 512 * 24;             // [32][513]  16416 f
    float* rawsh = hsh + 32 * 513;             // [32][25]     800 f
    float* bhs   = rawsh + 32 * 25;            // 24 f
    float* ghs   = bhs + 24;                   // 24 f
    float* behs  = ghs + 24;                   // 24 f

    const int tid = threadIdx.x;
    const int cta = blockIdx.x;
    const int dir = cta >> 6;                  // 0 = fwd, 1 = bwd
    const int j0  = (cta & 63) * 8;
    const int wsel = 2 * layer + dir;

    // ---- one-time loads ----
    const float* Whd = Wh + (size_t)wsel * 512 * 1536;
    for (int i = tid; i < 512 * 24; i += 256) {
        const int k = i / 24, lc = i - k * 24;
        const int col = ((lc >> 3) << 9) + j0 + (lc & 7);
        Wsh[i] = Whd[(size_t)k * 1536 + col];
    }
    if (tid < 24) {
        const int col = ((tid >> 3) << 9) + j0 + (tid & 7);
        bhs[tid]  = bh [(size_t)wsel * 1536 + col];
        ghs[tid]  = gh [(size_t)wsel * 1536 + col];
        behs[tid] = beh[(size_t)wsel * 1536 + col];
    }
    for (int i = tid; i < 32 * 512; i += 256)
        hsh[(i >> 9) * 513 + (i & 511)] = h0[(size_t)wsel * 32 * 512 + i];
    __syncthreads();

    unsigned epoch = 0;
    const int bA = tid & 31, cg = tid >> 5;    // phase-A map (cg<6 active)
    const int jB = tid & 7,  bB = tid >> 3;    // phase-B map (exactly 256)

    for (int s = 0; s < T_STEPS; ++s) {
        const int parity = s & 1;

        // zero other-parity stats (safe: last read before previous step's bar2)
        if (cta == 0) {
            const int base = (parity ^ 1) * (2 * 32 * 3 * 2);
            for (int i = tid; i < 2 * 32 * 3 * 2; i += 256) g_stats[base + i] = 0.f;
        }

        // -------- Phase A: GEMM tile (32 b x 24 cols) + partial LN stats ------
        if (cg < 6) {
            float a0 = bhs[cg * 4 + 0], a1 = bhs[cg * 4 + 1];
            float a2 = bhs[cg * 4 + 2], a3 = bhs[cg * 4 + 3];
            const float* hrow = hsh + bA * 513;
            const float* wp = Wsh + cg * 4;
#pragma unroll 8
            for (int k = 0; k < 512; ++k) {
                const float hv = hrow[k];
                const float4 w = *(const float4*)(wp + k * 24);
                a0 = fmaf(hv, w.x, a0); a1 = fmaf(hv, w.y, a1);
                a2 = fmaf(hv, w.z, a2); a3 = fmaf(hv, w.w, a3);
            }
            float* rp = rawsh + bA * 25 + cg * 4;
            rp[0] = a0; rp[1] = a1; rp[2] = a2; rp[3] = a3;
            const int gate = cg >> 1;
            float* st = g_stats + ((((parity * 2 + dir) * 32 + bA) * 3 + gate) * 2);
            atomicAdd(st,     a0 + a1 + a2 + a3);
            atomicAdd(st + 1, a0 * a0 + a1 * a1 + a2 * a2 + a3 * a3);
        }
        grid_bar(epoch);   // stats complete

        // -------- Phase B: normalize, gates, h_new for own 8 columns ----------
        {
            const float* st = g_stats + (((parity * 2 + dir) * 32 + bB) * 3) * 2;
            const float s0 = __ldcg(st + 0), q0 = __ldcg(st + 1);
            const float s1 = __ldcg(st + 2), q1 = __ldcg(st + 3);
            const float s2 = __ldcg(st + 4), q2 = __ldcg(st + 5);
            const float mu0 = s0 * (1.f / 512.f), v0 = q0 * (1.f / 512.f) - mu0 * mu0;
            const float mu1 = s1 * (1.f / 512.f), v1 = q1 * (1.f / 512.f) - mu1 * mu1;
            const float mu2 = s2 * (1.f / 512.f), v2 = q2 * (1.f / 512.f) - mu2 * mu2;
            const float r0 = rsqrtf(v0 + LN_EPS);
            const float r1 = rsqrtf(v1 + LN_EPS);
            const float r2 = rsqrtf(v2 + LN_EPS);

            const float* rp = rawsh + bB * 25;
            const float ahr = (rp[jB]      - mu0) * r0 * ghs[jB]      + behs[jB];
            const float ahz = (rp[8 + jB]  - mu1) * r1 * ghs[8 + jB]  + behs[8 + jB];
            const float ahn = (rp[16 + jB] - mu2) * r2 * ghs[16 + jB] + behs[16 + jB];

            const int tin = dir ? (T_STEPS - 1 - s) : s;
            const float* axp = g_ax + (((size_t)dir * T_STEPS + tin) * 32 + bB) * 1536
                                    + j0 + jB;
            const float axr = __ldg(axp);
            const float axz = __ldg(axp + 512);
            const float axn = __ldg(axp + 1024);

            const float r = 1.f / (1.f + __expf(-(axr + ahr)));
            const float z = 1.f / (1.f + __expf(-(axz + ahz)));
            const float n = tanhf(axn + r * ahn);
            const float hp = hsh[bB * 513 + j0 + jB];
            const float hn = fmaf(z, hp - n, n);   // (1-z)*n + z*h

            g_h[(dir * 32 + bB) * 512 + j0 + jB] = hn;
            if (layer == 0) {
                g_seq[(size_t)dir * T_STEPS * 32 * 512
                      + ((size_t)tin * 32 + bB) * 512 + j0 + jB] = hn;
            } else {
                out[((size_t)tin * 32 + bB) * 1024 + dir * 512 + j0 + jB] = hn;
            }
            if (write_hid && s == T_STEPS - 1)
                out[(size_t)16777216 + ((size_t)wsel * 32 + bB) * 512 + j0 + jB] = hn;
        }
        grid_bar(epoch);   // h complete

        if (s + 1 < T_STEPS) {
            const float* hg = g_h + dir * 32 * 512;
            for (int i = tid; i < 32 * 512; i += 256)
                hsh[(i >> 9) * 513 + (i & 511)] = __ldcg(hg + i);
            __syncthreads();
        }
    }
}

// ============================================================================
#define RS_BYTES ((512*24 + 32*513 + 32*25 + 24*3) * 4)

extern "C" void kernel_launch(void* const* d_in, const int* in_sizes, int n_in,
                              void* d_out, int out_size)
{
    const float* x   = (const float*)d_in[0];
    const float* h0  = (const float*)d_in[1];
    const float* Wx  = (const float*)d_in[2];
    const float* Wh  = (const float*)d_in[3];
    const float* bx  = (const float*)d_in[4];
    const float* bh  = (const float*)d_in[5];
    const float* gx  = (const float*)d_in[6];
    const float* bex = (const float*)d_in[7];
    const float* gh  = (const float*)d_in[8];
    const float* beh = (const float*)d_in[9];
    float* out = (float*)d_out;

    const int write_hid = (out_size >= 16777216 + 4 * 32 * 512) ? 1 : 0;

    cudaFuncSetAttribute(recurrent_kernel,
                         cudaFuncAttributeMaxDynamicSharedMemorySize, RS_BYTES);

    for (int layer = 0; layer < 2; ++layer) {
        dim3 gg(1536 / BN, 16384 / BM, 2);
        gemm_ax_kernel<<<gg, 256>>>(x, Wx, bx, layer);
        ln_ax_kernel<<<2 * 16384 * 3, 128>>>(gx, bex, layer);
        init_scratch_kernel<<<1, 256>>>();
        recurrent_kernel<<<NBLK, 256, RS_BYTES>>>(Wh, bh, gh, beh, h0, out,
                                                  layer, write_hid);
    }
}

// round 2
// speedup vs baseline: 1.3639x; 1.3639x over previous
#include <cuda_runtime.h>
#include <cstdint>

#define T_STEPS 512
#define BATCH   32
#define HID     512
#define LN_EPS  1e-5f
#define NBLK    128          // recurrent grid (64 CTAs per direction)
#define HP      516          // hsh pitch (floats): mult of 4, conflict-free

// ---------------- scratch (static device globals; no allocation) ----------------
__device__ float    g_ax[(size_t)2 * 512 * 32 * 1536];   // LN(x@Wx+bx) per dir
__device__ float    g_seq[(size_t)2 * 512 * 32 * 512];   // layer-0 outputs (fwd, bwd)
__device__ float    g_h[2 * 32 * 512];                   // current hidden state per dir
__device__ float    g_stats[2 * 2 * 32 * 3 * 2];         // [parity][dir][b][gate][sum,sq]
__device__ unsigned g_bar;                               // grid barrier counter

// ============================================================================
// Input GEMM: 128x128x16 fp32 tile, 256 threads, 8x8 microtile.
// C[dir][m][col] = A[m][:] @ Wx[wsel][:,col] + bx[wsel][col]
// ============================================================================
#define BM 128
#define BN 128
#define BK 16

__global__ __launch_bounds__(256, 2)
void gemm_ax_kernel(const float* __restrict__ x,
                    const float* __restrict__ Wx,
                    const float* __restrict__ bx,
                    int layer)
{
    const int dir = blockIdx.z;
    const float* A = (layer == 0) ? x
                                  : (g_seq + (size_t)dir * T_STEPS * BATCH * HID);
    const int wsel = 2 * layer + dir;
    const float* Bw   = Wx + (size_t)wsel * 512 * 1536;
    const float* bias = bx + (size_t)wsel * 1536;
    float* C = g_ax + (size_t)dir * 16384 * 1536;

    const int m0 = blockIdx.y * BM;
    const int n0 = blockIdx.x * BN;

    __shared__ float As[BK][BM];
    __shared__ float Bs[BK][BN];

    const int tid = threadIdx.x;
    // loader maps
    const int arow = tid & 127;          // conflict-free STS (consecutive rows/warp)
    const int akseg = tid >> 7;          // 0..1 -> k offsets {0,8}
    const int bnq = tid & 31;
    const int bk  = tid >> 5;            // 0..7 -> k rows {bk, bk+8}
    // compute map
    const int tx = tid & 15;
    const int ty = tid >> 4;

    float acc[8][8];
#pragma unroll
    for (int i = 0; i < 8; ++i)
#pragma unroll
        for (int j = 0; j < 8; ++j) acc[i][j] = 0.f;

    for (int k0 = 0; k0 < 512; k0 += BK) {
        float4 a04 = *(const float4*)(A + (size_t)(m0 + arow) * 512 + k0 + akseg * 8);
        float4 a14 = *(const float4*)(A + (size_t)(m0 + arow) * 512 + k0 + akseg * 8 + 4);
        float4 bv0 = *(const float4*)(Bw + (size_t)(k0 + bk) * 1536 + n0 + bnq * 4);
        float4 bv1 = *(const float4*)(Bw + (size_t)(k0 + bk + 8) * 1536 + n0 + bnq * 4);

        As[akseg * 8 + 0][arow] = a04.x;
        As[akseg * 8 + 1][arow] = a04.y;
        As[akseg * 8 + 2][arow] = a04.z;
        As[akseg * 8 + 3][arow] = a04.w;
        As[akseg * 8 + 4][arow] = a14.x;
        As[akseg * 8 + 5][arow] = a14.y;
        As[akseg * 8 + 6][arow] = a14.z;
        As[akseg * 8 + 7][arow] = a14.w;
        *(float4*)&Bs[bk][bnq * 4]     = bv0;
        *(float4*)&Bs[bk + 8][bnq * 4] = bv1;
        __syncthreads();

#pragma unroll
        for (int kk = 0; kk < BK; ++kk) {
            float ar[8], br[8];
            float4 t0 = *(const float4*)&As[kk][ty * 4];
            float4 t1 = *(const float4*)&As[kk][64 + ty * 4];
            ar[0]=t0.x; ar[1]=t0.y; ar[2]=t0.z; ar[3]=t0.w;
            ar[4]=t1.x; ar[5]=t1.y; ar[6]=t1.z; ar[7]=t1.w;
            float4 u0 = *(const float4*)&Bs[kk][tx * 4];
            float4 u1 = *(const float4*)&Bs[kk][64 + tx * 4];
            br[0]=u0.x; br[1]=u0.y; br[2]=u0.z; br[3]=u0.w;
            br[4]=u1.x; br[5]=u1.y; br[6]=u1.z; br[7]=u1.w;
#pragma unroll
            for (int i = 0; i < 8; ++i)
#pragma unroll
                for (int j = 0; j < 8; ++j)
                    acc[i][j] = fmaf(ar[i], br[j], acc[i][j]);
        }
        __syncthreads();
    }

    const float4 bb0 = *(const float4*)(bias + n0 + tx * 4);
    const float4 bb1 = *(const float4*)(bias + n0 + 64 + tx * 4);
#pragma unroll
    for (int i = 0; i < 8; ++i) {
        const int row = m0 + ((i < 4) ? (ty * 4 + i) : (64 + ty * 4 + i - 4));
        float4 o0, o1;
        o0.x = acc[i][0] + bb0.x; o0.y = acc[i][1] + bb0.y;
        o0.z = acc[i][2] + bb0.z; o0.w = acc[i][3] + bb0.w;
        o1.x = acc[i][4] + bb1.x; o1.y = acc[i][5] + bb1.y;
        o1.z = acc[i][6] + bb1.z; o1.w = acc[i][7] + bb1.w;
        *(float4*)(C + (size_t)row * 1536 + n0 + tx * 4)      = o0;
        *(float4*)(C + (size_t)row * 1536 + n0 + 64 + tx * 4) = o1;
    }
}

// ============================================================================
// LayerNorm over each 512-wide gate chunk of g_ax (in place), then *gx + bex.
// ============================================================================
__global__ void ln_ax_kernel(const float* __restrict__ gx,
                             const float* __restrict__ bex,
                             int layer)
{
    const int id   = blockIdx.x;
    const int gate = id % 3;
    const int row  = (id / 3) & 16383;
    const int dir  = id / (3 * 16384);
    const int wsel = 2 * layer + dir;

    float* p = g_ax + (size_t)dir * 16384 * 1536 + (size_t)row * 1536 + gate * 512;
    const float* gp = gx  + (size_t)wsel * 1536 + gate * 512;
    const float* bp = bex + (size_t)wsel * 1536 + gate * 512;

    const int tid = threadIdx.x;               // 128 threads * 4 elems
    float4 v = *(const float4*)(p + tid * 4);
    float s  = v.x + v.y + v.z + v.w;
    float ss = v.x * v.x + v.y * v.y + v.z * v.z + v.w * v.w;
#pragma unroll
    for (int o = 16; o; o >>= 1) {
        s  += __shfl_xor_sync(0xffffffffu, s,  o);
        ss += __shfl_xor_sync(0xffffffffu, ss, o);
    }
    __shared__ float red[8];
    if ((tid & 31) == 0) { red[tid >> 5] = s; red[4 + (tid >> 5)] = ss; }
    __syncthreads();
    const float ts  = red[0] + red[1] + red[2] + red[3];
    const float tss = red[4] + red[5] + red[6] + red[7];
    const float mu   = ts * (1.f / 512.f);
    const float var  = tss * (1.f / 512.f) - mu * mu;
    const float rstd = rsqrtf(var + LN_EPS);

    const float4 g4 = *(const float4*)(gp + tid * 4);
    const float4 b4 = *(const float4*)(bp + tid * 4);
    float4 o;
    o.x = (v.x - mu) * rstd * g4.x + b4.x;
    o.y = (v.y - mu) * rstd * g4.y + b4.y;
    o.z = (v.z - mu) * rstd * g4.z + b4.z;
    o.w = (v.w - mu) * rstd * g4.w + b4.w;
    *(float4*)(p + tid * 4) = o;
}

// ============================================================================
__global__ void init_scratch_kernel()
{
    const int i = threadIdx.x;
    if (i == 0) g_bar = 0u;
    for (int k = i; k < 2 * 2 * 32 * 3 * 2; k += blockDim.x) g_stats[k] = 0.f;
}

// ============================================================================
// Persistent recurrent kernel.
// 128 CTAs x 256 thr; CTA (dir,c) owns 24 weight columns (8 per gate).
// Phase A: balanced 8-warp GEMM (3 cols/thread, Wh col-major in SMEM).
// ============================================================================
__device__ __forceinline__ void grid_bar(unsigned& target)
{
    __threadfence();
    __syncthreads();
    if (threadIdx.x == 0) {
        atomicAdd(&g_bar, 1u);
        target += (unsigned)NBLK;
        while (__ldcg(&g_bar) < target) __nanosleep(32);
        __threadfence();
    }
    __syncthreads();
}

__global__ __launch_bounds__(256)
void recurrent_kernel(const float* __restrict__ Wh,
                      const float* __restrict__ bh,
                      const float* __restrict__ gh,
                      const float* __restrict__ beh,
                      const float* __restrict__ h0,
                      float* __restrict__ out,
                      int layer, int write_hid)
{
    extern __shared__ float sm[];
    float* Wsh   = sm;                         // [24][512] col-major  12288 f
    float* hsh   = Wsh + 24 * 512;             // [32][HP]             16512 f
    float* rawsh = hsh + 32 * HP;              // [32][25]               800 f
    float* bhs   = rawsh + 32 * 25;            // 24 f
    float* ghs   = bhs + 24;                   // 24 f
    float* behs  = ghs + 24;                   // 24 f

    const int tid = threadIdx.x;
    const int cta = blockIdx.x;
    const int dir = cta >> 6;                  // 0 = fwd, 1 = bwd
    const int j0  = (cta & 63) * 8;
    const int wsel = 2 * layer + dir;

    // ---- one-time loads ----
    const float* Whd = Wh + (size_t)wsel * 512 * 1536;
    for (int i = tid; i < 24 * 512; i += 256) {
        const int c = i >> 9, k = i & 511;
        const int col = ((c >> 3) << 9) + j0 + (c & 7);
        Wsh[i] = Whd[(size_t)k * 1536 + col];
    }
    if (tid < 24) {
        const int col = ((tid >> 3) << 9) + j0 + (tid & 7);
        bhs[tid]  = bh [(size_t)wsel * 1536 + col];
        ghs[tid]  = gh [(size_t)wsel * 1536 + col];
        behs[tid] = beh[(size_t)wsel * 1536 + col];
    }
    for (int i = tid; i < 32 * 128; i += 256) {
        const int b = i >> 7, q = i & 127;
        *(float4*)&hsh[b * HP + q * 4] =
            *(const float4*)(h0 + (size_t)wsel * 32 * 512 + b * 512 + q * 4);
    }
    __syncthreads();

    unsigned target = 0;
    // phase-A map: b over lanes, 3 columns per thread
    const int bA = tid & 31;
    const int c0 = (tid >> 5) * 3;             // 0,3,...,21
    // phase-B map
    const int jB = tid & 7, bB = tid >> 3;

    const float* hrow = hsh + bA * HP;
    const float* w0 = Wsh + c0 * 512;
    const float* w1 = w0 + 512;
    const float* w2 = w1 + 512;

    for (int s = 0; s < T_STEPS; ++s) {
        const int parity = s & 1;
        const int tin = dir ? (T_STEPS - 1 - s) : s;

        // prefetch ax for phase B (DRAM latency hides under phase-A GEMM)
        const float* axp = g_ax + (((size_t)dir * T_STEPS + tin) * 32 + bB) * 1536
                                + j0 + jB;
        const float axr = __ldg(axp);
        const float axz = __ldg(axp + 512);
        const float axn = __ldg(axp + 1024);

        // zero other-parity stats (safe: last read before previous step's bar2)
        if (cta == 0) {
            const int base = (parity ^ 1) * (2 * 32 * 3 * 2);
            for (int i = tid; i < 2 * 32 * 3 * 2; i += 256) g_stats[base + i] = 0.f;
        }

        // -------- Phase A: 32b x 24col GEMM, balanced across all 8 warps -----
        {
            float s0a = bhs[c0],     s0b = 0.f;
            float s1a = bhs[c0 + 1], s1b = 0.f;
            float s2a = bhs[c0 + 2], s2b = 0.f;
#pragma unroll 4
            for (int k = 0; k < 512; k += 4) {
                const float4 h4 = *(const float4*)(hrow + k);
                const float4 wa = *(const float4*)(w0 + k);
                const float4 wb = *(const float4*)(w1 + k);
                const float4 wc = *(const float4*)(w2 + k);
                s0a = fmaf(h4.x, wa.x, s0a); s0b = fmaf(h4.y, wa.y, s0b);
                s0a = fmaf(h4.z, wa.z, s0a); s0b = fmaf(h4.w, wa.w, s0b);
                s1a = fmaf(h4.x, wb.x, s1a); s1b = fmaf(h4.y, wb.y, s1b);
                s1a = fmaf(h4.z, wb.z, s1a); s1b = fmaf(h4.w, wb.w, s1b);
                s2a = fmaf(h4.x, wc.x, s2a); s2b = fmaf(h4.y, wc.y, s2b);
                s2a = fmaf(h4.z, wc.z, s2a); s2b = fmaf(h4.w, wc.w, s2b);
            }
            float* rp = rawsh + bA * 25 + c0;
            rp[0] = s0a + s0b; rp[1] = s1a + s1b; rp[2] = s2a + s2b;
        }
        __syncthreads();

        // -------- LN stats from rawsh: 96 threads, one (b,gate) each ---------
        if (tid < 96) {
            const int g = tid >> 5, b = tid & 31;
            const float* rp = rawsh + b * 25 + g * 8;
            float sum = 0.f, sq = 0.f;
#pragma unroll
            for (int i = 0; i < 8; ++i) { const float v = rp[i]; sum += v; sq += v * v; }
            float* st = g_stats + ((((parity * 2 + dir) * 32 + b) * 3 + g) * 2);
            atomicAdd(st, sum);
            atomicAdd(st + 1, sq);
        }
        grid_bar(target);   // stats complete

        // -------- Phase B: normalize, gates, h_new for own 8 columns ----------
        {
            const float* st = g_stats + (((parity * 2 + dir) * 32 + bB) * 3) * 2;
            const float s0 = __ldcg(st + 0), q0 = __ldcg(st + 1);
            const float s1 = __ldcg(st + 2), q1 = __ldcg(st + 3);
            const float s2 = __ldcg(st + 4), q2 = __ldcg(st + 5);
            const float mu0 = s0 * (1.f / 512.f), v0 = q0 * (1.f / 512.f) - mu0 * mu0;
            const float mu1 = s1 * (1.f / 512.f), v1 = q1 * (1.f / 512.f) - mu1 * mu1;
            const float mu2 = s2 * (1.f / 512.f), v2 = q2 * (1.f / 512.f) - mu2 * mu2;
            const float r0 = rsqrtf(v0 + LN_EPS);
            const float r1 = rsqrtf(v1 + LN_EPS);
            const float r2 = rsqrtf(v2 + LN_EPS);

            const float* rp = rawsh + bB * 25;
            const float ahr = (rp[jB]      - mu0) * r0 * ghs[jB]      + behs[jB];
            const float ahz = (rp[8 + jB]  - mu1) * r1 * ghs[8 + jB]  + behs[8 + jB];
            const float ahn = (rp[16 + jB] - mu2) * r2 * ghs[16 + jB] + behs[16 + jB];

            const float r = 1.f / (1.f + __expf(-(axr + ahr)));
            const float z = 1.f / (1.f + __expf(-(axz + ahz)));
            const float n = tanhf(axn + r * ahn);
            const float hp = hsh[bB * HP + j0 + jB];
            const float hn = fmaf(z, hp - n, n);   // (1-z)*n + z*h

            g_h[(dir * 32 + bB) * 512 + j0 + jB] = hn;
            if (layer == 0) {
                g_seq[(size_t)dir * T_STEPS * 32 * 512
                      + ((size_t)tin * 32 + bB) * 512 + j0 + jB] = hn;
            } else {
                out[((size_t)tin * 32 + bB) * 1024 + dir * 512 + j0 + jB] = hn;
            }
            if (write_hid && s == T_STEPS - 1)
                out[(size_t)16777216 + ((size_t)wsel * 32 + bB) * 512 + j0 + jB] = hn;
        }
        grid_bar(target);   // h complete

        if (s + 1 < T_STEPS) {
            const float* hg = g_h + dir * 32 * 512;
            for (int i = tid; i < 32 * 128; i += 256) {
                const int b = i >> 7, q = i & 127;
                const float4 v = __ldcg((const float4*)(hg + b * 512 + q * 4));
                *(float4*)&hsh[b * HP + q * 4] = v;
            }
            __syncthreads();
        }
    }
}

// ============================================================================
#define RS_BYTES ((24*512 + 32*HP + 32*25 + 24*3) * 4)

extern "C" void kernel_launch(void* const* d_in, const int* in_sizes, int n_in,
                              void* d_out, int out_size)
{
    const float* x   = (const float*)d_in[0];
    const float* h0  = (const float*)d_in[1];
    const float* Wx  = (const float*)d_in[2];
    const float* Wh  = (const float*)d_in[3];
    const float* bx  = (const float*)d_in[4];
    const float* bh  = (const float*)d_in[5];
    const float* gx  = (const float*)d_in[6];
    const float* bex = (const float*)d_in[7];
    const float* gh  = (const float*)d_in[8];
    const float* beh = (const float*)d_in[9];
    float* out = (float*)d_out;

    const int write_hid = (out_size >= 16777216 + 4 * 32 * 512) ? 1 : 0;

    cudaFuncSetAttribute(recurrent_kernel,
                         cudaFuncAttributeMaxDynamicSharedMemorySize, RS_BYTES);

    for (int layer = 0; layer < 2; ++layer) {
        dim3 gg(1536 / BN, 16384 / BM, 2);
        gemm_ax_kernel<<<gg, 256>>>(x, Wx, bx, layer);
        ln_ax_kernel<<<2 * 16384 * 3, 128>>>(gx, bex, layer);
        init_scratch_kernel<<<1, 256>>>();
        recurrent_kernel<<<NBLK, 256, RS_BYTES>>>(Wh, bh, gh, beh, h0, out,
                                                  layer, write_hid);
    }
}